// round 10
// baseline (speedup 1.0000x reference)
#include <cuda_runtime.h>
#include <cstdint>
#include <math.h>

// Problem dims
#define SQ  512
#define DD  3072
#define DHH 256
#define EE  4
#define FF  8192
#define RR  16
#define H1N 128

// SIMT GEMM tiling (gating)
#define BK 16
#define LDP 68

// ================= device scratch =================
__device__ float g_h1x[SQ*H1N];
__device__ float g_hh[H1N];
__device__ float g_hp[EE*H1N];
__device__ float g_cc[2];
__device__ float g_logits[EE*SQ];
__device__ int   g_cnt[EE];
__device__ int   g_tok[EE*SQ];
__device__ float g_wgt[EE*SQ];
__device__ int   g_slot[EE*SQ];
__device__ float g_xa[EE*SQ*32];          // 16 gate + 16 up LoRA x-projections
__device__ float g_had[EE*SQ*RR];         // down LoRA h-projection
__device__ float g_hbuf[(size_t)EE*SQ*FF];// silu(g)*u rows per (e, listpos)
__device__ float g_scr[2*SQ*DD];          // slot0/slot1 weighted expert outputs

// ================= mma helpers =================
__device__ __forceinline__ uint32_t f2tf32(float f) {
    uint32_t u;
    asm("cvt.rna.tf32.f32 %0, %1;" : "=r"(u) : "f"(f));
    return u;
}
__device__ __forceinline__ void mma8(float* c, const uint32_t* a, uint32_t b0, uint32_t b1) {
    asm volatile(
        "mma.sync.aligned.m16n8k8.row.col.f32.tf32.tf32.f32 "
        "{%0,%1,%2,%3}, {%4,%5,%6,%7}, {%8,%9}, {%0,%1,%2,%3};"
        : "+f"(c[0]), "+f"(c[1]), "+f"(c[2]), "+f"(c[3])
        : "r"(a[0]), "r"(a[1]), "r"(a[2]), "r"(a[3]), "r"(b0), "r"(b1));
}
// permuted store: element k of a 16-wide chunk goes to pos (k&3)*4 + (k>>2).
// thread holds float4 = k in [q*4, q*4+4) -> positions {q, 4+q, 8+q, 12+q}
__device__ __forceinline__ void sts_perm(uint32_t* row, int q, float4 v) {
    row[q]      = f2tf32(v.x);
    row[4 + q]  = f2tf32(v.y);
    row[8 + q]  = f2tf32(v.z);
    row[12 + q] = f2tf32(v.w);
}

// ================= K0: history/persona projections + LN-fold constants =================
__global__ void k0_hist_persona(const float* __restrict__ hist,
                                const float* __restrict__ persona,
                                const float* __restrict__ fw1h,
                                const float* __restrict__ fw1p,
                                const float* __restrict__ lng,
                                const float* __restrict__ lnb,
                                const float* __restrict__ gw) {
    __shared__ float r3[128], r2[128];
    int k = threadIdx.x;  // 128
    float acc = 0.f;
    const float4* h4 = (const float4*)hist;
    const float4* w4 = (const float4*)(fw1h + (size_t)k*DHH);
    for (int i = 0; i < DHH/4; i++) {
        float4 a = h4[i], b = w4[i];
        acc += a.x*b.x + a.y*b.y + a.z*b.z + a.w*b.w;
    }
    g_hh[k] = acc;
    for (int e = 0; e < EE; e++) {
        const float4* p4 = (const float4*)(persona + (size_t)e*DD);
        const float4* q4 = (const float4*)(fw1p + (size_t)k*DD);
        float a2 = 0.f;
        for (int i = 0; i < DD/4; i++) {
            float4 a = p4[i], b = q4[i];
            a2 += a.x*b.x + a.y*b.y + a.z*b.z + a.w*b.w;
        }
        g_hp[e*H1N + k] = a2;
    }
    float c3 = 0.f, c2 = 0.f;
    for (int d = k; d < DD; d += 128) { c3 += lng[d]*gw[d]; c2 += lnb[d]*gw[d]; }
    r3[k] = c3; r2[k] = c2; __syncthreads();
    for (int o = 64; o > 0; o >>= 1) { if (k < o) { r3[k] += r3[k+o]; r2[k] += r2[k+o]; } __syncthreads(); }
    if (k == 0) { g_cc[0] = r3[0]; g_cc[1] = r2[0]; }
}

// ================= K1: tiled SGEMM  h1x[s,k] = x . fw1x^T =================
__global__ __launch_bounds__(256) void k1t(const float* __restrict__ x,
                                           const float* __restrict__ fw1x) {
    int n0 = blockIdx.x * 64, m0 = blockIdx.y * 64;
    __shared__ float Xs[BK][LDP], Ws[BK][LDP];
    int tid = threadIdx.x;
    int row = tid >> 2, qv = tid & 3, ty = tid >> 4, tx = tid & 15;
    const float* xp = x + (size_t)(m0+row)*DD + qv*4;
    const float* wp = fw1x + (size_t)(n0+row)*DD + qv*4;
    float acc[4][4] = {};
    for (int kk = 0; kk < DD; kk += BK) {
        float4 a = *(const float4*)(xp + kk);
        float4 b = *(const float4*)(wp + kk);
        __syncthreads();
        Xs[qv*4+0][row]=a.x; Xs[qv*4+1][row]=a.y; Xs[qv*4+2][row]=a.z; Xs[qv*4+3][row]=a.w;
        Ws[qv*4+0][row]=b.x; Ws[qv*4+1][row]=b.y; Ws[qv*4+2][row]=b.z; Ws[qv*4+3][row]=b.w;
        __syncthreads();
        #pragma unroll
        for (int k = 0; k < BK; k++) {
            float4 av = *(const float4*)&Xs[k][ty*4];
            float4 bv = *(const float4*)&Ws[k][tx*4];
            float am[4] = {av.x, av.y, av.z, av.w};
            float bm[4] = {bv.x, bv.y, bv.z, bv.w};
            #pragma unroll
            for (int i = 0; i < 4; i++)
                #pragma unroll
                for (int j = 0; j < 4; j++)
                    acc[i][j] += am[i]*bm[j];
        }
    }
    #pragma unroll
    for (int i = 0; i < 4; i++) {
        int m = m0 + ty*4 + i;
        *(float4*)(g_h1x + (size_t)m*H1N + n0 + tx*4) =
            make_float4(acc[i][0], acc[i][1], acc[i][2], acc[i][3]);
    }
}

// ================= K2: batched fused MLP -> LN-folded logit =================
__global__ __launch_bounds__(256) void k2b(const float* __restrict__ fb1,
                                           const float* __restrict__ fw2,
                                           const float* __restrict__ fb2,
                                           const float* __restrict__ lng,
                                           const float* __restrict__ gw,
                                           const float* __restrict__ gb) {
    int e = blockIdx.y;
    int s0 = blockIdx.x * 8;
    int tid = threadIdx.x;
    __shared__ float h1r[8][H1N];
    __shared__ float red[8][8][3];
    for (int i = tid; i < 8*H1N; i += 256) {
        int t = i >> 7, k = i & 127;
        float v = g_h1x[(size_t)(s0+t)*H1N + k] + g_hh[k] + fb1[k] + g_hp[e*H1N + k];
        h1r[t][k] = fmaxf(v, 0.f);
    }
    __syncthreads();
    float s1[8] = {}, s2[8] = {}, s3[8] = {};
    for (int i = 0; i < DD/256; i++) {
        int d = tid + i*256;
        const float4* wr = (const float4*)(fw2 + (size_t)d*H1N);
        float acc[8] = {};
        #pragma unroll 8
        for (int k4 = 0; k4 < H1N/4; k4++) {
            float4 b = wr[k4];
            #pragma unroll
            for (int t = 0; t < 8; t++) {
                float4 a = *(const float4*)&h1r[t][k4*4];
                acc[t] += a.x*b.x + a.y*b.y + a.z*b.z + a.w*b.w;
            }
        }
        float bias = fb2[d], c1 = lng[d]*gw[d];
        #pragma unroll
        for (int t = 0; t < 8; t++) {
            float f = fmaxf(acc[t] + bias, 0.f);
            s1[t] += f; s2[t] += f*f; s3[t] += f*c1;
        }
    }
    #pragma unroll
    for (int t = 0; t < 8; t++) {
        #pragma unroll
        for (int o = 16; o; o >>= 1) {
            s1[t] += __shfl_down_sync(~0u, s1[t], o);
            s2[t] += __shfl_down_sync(~0u, s2[t], o);
            s3[t] += __shfl_down_sync(~0u, s3[t], o);
        }
    }
    int wid = tid >> 5, lane = tid & 31;
    if (lane == 0) {
        #pragma unroll
        for (int t = 0; t < 8; t++) {
            red[wid][t][0] = s1[t]; red[wid][t][1] = s2[t]; red[wid][t][2] = s3[t];
        }
    }
    __syncthreads();
    if (tid < 8) {
        float a = 0.f, b = 0.f, c = 0.f;
        #pragma unroll
        for (int w = 0; w < 8; w++) { a += red[w][tid][0]; b += red[w][tid][1]; c += red[w][tid][2]; }
        float mean = a * (1.f/DD);
        float var  = b * (1.f/DD) - mean*mean;
        float rstd = rsqrtf(var + 1e-5f);
        g_logits[e*SQ + s0 + tid] = rstd*(c - mean*g_cc[0]) + g_cc[1] + gb[0];
    }
}

// ================= K3: softmax / top-2 / routing / entropy =================
__global__ void k3_route(float* __restrict__ d_out, int out_size) {
    int s = threadIdx.x;  // 512
    __shared__ float er[SQ];
    if (s < EE) g_cnt[s] = 0;
    __syncthreads();
    float l[EE];
    #pragma unroll
    for (int e = 0; e < EE; e++) l[e] = g_logits[e*SQ + s];
    float m = fmaxf(fmaxf(l[0], l[1]), fmaxf(l[2], l[3]));
    float p[EE]; float psum = 0.f;
    #pragma unroll
    for (int e = 0; e < EE; e++) { p[e] = expf(l[e]-m); psum += p[e]; }
    float inv = 1.f/psum;
    float ent = 0.f;
    #pragma unroll
    for (int e = 0; e < EE; e++) { p[e] *= inv; ent -= p[e]*logf(p[e] + 1e-9f); }
    int e0 = 0; float b0 = p[0];
    #pragma unroll
    for (int e = 1; e < EE; e++) if (p[e] > b0) { b0 = p[e]; e0 = e; }
    int e1 = -1; float b1 = -1.f;
    #pragma unroll
    for (int e = 0; e < EE; e++) if (e != e0 && p[e] > b1) { b1 = p[e]; e1 = e; }
    int i0 = atomicAdd(&g_cnt[e0], 1);
    g_tok[e0*SQ + i0] = s; g_wgt[e0*SQ + i0] = p[e0]; g_slot[e0*SQ + i0] = 0;
    int i1 = atomicAdd(&g_cnt[e1], 1);
    g_tok[e1*SQ + i1] = s; g_wgt[e1*SQ + i1] = p[e1]; g_slot[e1*SQ + i1] = 1;
    er[s] = ent; __syncthreads();
    for (int o = 256; o > 0; o >>= 1) { if (s < o) er[s] += er[s+o]; __syncthreads(); }
    if (s == 0 && out_size > SQ*DD) d_out[SQ*DD] = er[0] * (1.f/SQ);
}

// ================= E1: x LoRA projections (gate/up) =================
__global__ void e1_xa(const float* __restrict__ x,
                      const float* __restrict__ Ag,
                      const float* __restrict__ Au) {
    int e = blockIdx.y, i = blockIdx.x;
    if (i >= g_cnt[e]) return;
    int tok = g_tok[e*SQ + i];
    const float4* xr = (const float4*)(x + (size_t)tok*DD);
    int warp = threadIdx.x >> 5, lane = threadIdx.x & 31;
    for (int o = warp; o < 32; o += 4) {
        const float* A = (o < 16) ? Ag : Au;
        int r = o & 15;
        const float4* ar = (const float4*)(A + ((size_t)e*RR + r)*DD);
        float acc = 0.f;
        for (int qv = lane; qv < DD/4; qv += 32) {
            float4 a = xr[qv], b = ar[qv];
            acc += a.x*b.x + a.y*b.y + a.z*b.z + a.w*b.w;
        }
        #pragma unroll
        for (int off = 16; off; off >>= 1) acc += __shfl_down_sync(0xffffffffu, acc, off);
        if (lane == 0) g_xa[((size_t)e*SQ + i)*32 + o] = acc;
    }
}

// ================= E2: mma.sync tf32 gate+up, 512 thr, perm layout, 1 sync/chunk =================
// Block tile 128(m) x 64(n). 16 warps as 4m x 4n, warp tile 32x16.
// K chunks of 16: DD/16 = 192 main + chunk 192 (gate LoRA) + 193 (up LoRA).
__global__ __launch_bounds__(512) void e2_mma(const float* __restrict__ x,
                                              const float* __restrict__ Wg,
                                              const float* __restrict__ Wu,
                                              const float* __restrict__ Bg,
                                              const float* __restrict__ Bu) {
    int e = blockIdx.z;
    int n_e = g_cnt[e];
    int m0 = blockIdx.x * 128;
    if (m0 >= n_e) return;
    int n0 = blockIdx.y * 64;
    __shared__ uint32_t As[2][128*16];
    __shared__ uint32_t Gs[2][64*16];
    __shared__ uint32_t Us[2][64*16];
    __shared__ int toks[128];
    int tid = threadIdx.x, lane = tid & 31, wid = tid >> 5;
    int wm = wid >> 2, wn = wid & 3;
    if (tid < 128) toks[tid] = g_tok[e*SQ + min(m0 + tid, n_e - 1)];
    __syncthreads();

    const int NCH = DD/16;   // 192
    const int TCH = NCH + 2;

    int arow = tid >> 2, aq = tid & 3;          // A: 128 rows x 4 quads
    bool isG = tid < 256;
    int grow = (tid & 255) >> 2, gq = tid & 3;  // G (t<256) / U (t>=256): 64 rows x 4 quads
    int liA = e*SQ + min(m0 + arow, n_e - 1);

    float4 rA, rW;
    auto ldg_chunk = [&](int kc) {
        if (kc < NCH) {
            int kb = kc*16;
            rA = *(const float4*)(x + (size_t)toks[arow]*DD + kb + aq*4);
            const float* Wsrc = isG ? Wg : Wu;
            rW = *(const float4*)(Wsrc + ((size_t)e*FF + n0 + grow)*DD + kb + gq*4);
        } else if (kc == NCH) {
            rA = *(const float4*)(g_xa + (size_t)liA*32 + aq*4);
            if (isG) rW = *(const float4*)(Bg + ((size_t)e*FF + n0 + grow)*RR + gq*4);
        } else {
            rA = *(const float4*)(g_xa + (size_t)liA*32 + 16 + aq*4);
            if (!isG) rW = *(const float4*)(Bu + ((size_t)e*FF + n0 + grow)*RR + gq*4);
        }
    };
    auto sts_chunk = [&](int s, int kc) {
        sts_perm(&As[s][arow*16], aq, rA);
        bool doW = (kc < NCH) || (kc == NCH && isG) || (kc == NCH+1 && !isG);
        if (doW) {
            uint32_t* wrow = isG ? &Gs[s][grow*16] : &Us[s][grow*16];
            sts_perm(wrow, gq, rW);
        }
    };

    float accg[2][2][4] = {}, accu[2][2][4] = {};

    ldg_chunk(0); sts_chunk(0, 0);
    ldg_chunk(1);
    __syncthreads();

    int r = lane & 3, rowq = lane >> 2;
    for (int kc = 0; kc < TCH; kc++) {
        int s = kc & 1;
        bool dog = (kc != NCH+1), dou = (kc != NCH);
        uint4 fa[2][2];
        #pragma unroll
        for (int mt = 0; mt < 2; mt++) {
            int rb = wm*32 + mt*16 + rowq;
            fa[mt][0] = *(const uint4*)&As[s][rb*16 + r*4];
            fa[mt][1] = *(const uint4*)&As[s][(rb+8)*16 + r*4];
        }
        #pragma unroll
        for (int nt = 0; nt < 2; nt++) {
            int nrow = wn*16 + nt*8 + rowq;
            uint4 fg = make_uint4(0,0,0,0), fu = make_uint4(0,0,0,0);
            if (dog) fg = *(const uint4*)&Gs[s][nrow*16 + r*4];
            if (dou) fu = *(const uint4*)&Us[s][nrow*16 + r*4];
            #pragma unroll
            for (int mt = 0; mt < 2; mt++) {
                uint32_t a0[4] = {fa[mt][0].x, fa[mt][1].x, fa[mt][0].y, fa[mt][1].y}; // ks0
                uint32_t a1[4] = {fa[mt][0].z, fa[mt][1].z, fa[mt][0].w, fa[mt][1].w}; // ks1
                if (dog) { mma8(accg[mt][nt], a0, fg.x, fg.y); mma8(accg[mt][nt], a1, fg.z, fg.w); }
                if (dou) { mma8(accu[mt][nt], a0, fu.x, fu.y); mma8(accu[mt][nt], a1, fu.z, fu.w); }
            }
        }
        if (kc + 1 < TCH) sts_chunk((kc + 1) & 1, kc + 1);
        if (kc + 2 < TCH) ldg_chunk(kc + 2);
        __syncthreads();
    }

    // epilogue: silu(g)*u -> g_hbuf
    #pragma unroll
    for (int mt = 0; mt < 2; mt++) {
        #pragma unroll
        for (int half = 0; half < 2; half++) {
            int mrow = wm*32 + mt*16 + rowq + half*8;
            int m = m0 + mrow;
            if (m < n_e) {
                float* hr = g_hbuf + ((size_t)e*SQ + m)*FF + n0;
                #pragma unroll
                for (int nt = 0; nt < 2; nt++) {
                    int col = wn*16 + nt*8 + 2*r;
                    float gg0 = accg[mt][nt][half*2+0], uu0 = accu[mt][nt][half*2+0];
                    float gg1 = accg[mt][nt][half*2+1], uu1 = accu[mt][nt][half*2+1];
                    float2 hv;
                    hv.x = gg0*uu0/(1.f + __expf(-gg0));
                    hv.y = gg1*uu1/(1.f + __expf(-gg1));
                    *(float2*)(hr + col) = hv;
                }
            }
        }
    }
}

// ================= E3: h LoRA projection (down) =================
__global__ void e3_ha(const float* __restrict__ Ad) {
    int e = blockIdx.y, i = blockIdx.x;
    if (i >= g_cnt[e]) return;
    const float4* hr = (const float4*)(g_hbuf + ((size_t)e*SQ + i)*FF);
    int warp = threadIdx.x >> 5, lane = threadIdx.x & 31;
    for (int r = warp; r < RR; r += 4) {
        const float4* ar = (const float4*)(Ad + ((size_t)e*RR + r)*FF);
        float acc = 0.f;
        for (int qv = lane; qv < FF/4; qv += 32) {
            float4 a = hr[qv], b = ar[qv];
            acc += a.x*b.x + a.y*b.y + a.z*b.z + a.w*b.w;
        }
        #pragma unroll
        for (int off = 16; off; off >>= 1) acc += __shfl_down_sync(0xffffffffu, acc, off);
        if (lane == 0) g_had[((size_t)e*SQ + i)*RR + r] = acc;
    }
}

// ================= E4: mma.sync tf32 down, 512 thr, perm layout, 1 sync/chunk =================
// Block tile 128(m) x 64(n of D). K chunks of 16: FF/16 = 512 main + 1 LoRA.
__global__ __launch_bounds__(512) void e4_mma(const float* __restrict__ Wd,
                                              const float* __restrict__ Bd) {
    int e = blockIdx.z;
    int n_e = g_cnt[e];
    int m0 = blockIdx.x * 128;
    if (m0 >= n_e) return;
    int n0 = blockIdx.y * 64;
    __shared__ uint32_t As[2][128*16];
    __shared__ uint32_t Ws[2][64*16];
    __shared__ int   toks[128];
    __shared__ float wts[128];
    __shared__ int   slts[128];
    int tid = threadIdx.x, lane = tid & 31, wid = tid >> 5;
    int wm = wid >> 2, wn = wid & 3;
    if (tid < 128) {
        int li = e*SQ + min(m0 + tid, n_e - 1);
        toks[tid] = g_tok[li]; wts[tid] = g_wgt[li]; slts[tid] = g_slot[li];
    }
    __syncthreads();

    const int NCH = FF/16;   // 512
    const int TCH = NCH + 1;

    int arow = tid >> 2, aq = tid & 3;
    bool isW = tid < 256;
    int grow = (tid & 255) >> 2, gq = tid & 3;
    int liA = e*SQ + min(m0 + arow, n_e - 1);

    float4 rA, rW;
    auto ldg_chunk = [&](int kc) {
        if (kc < NCH) {
            int kb = kc*16;
            rA = *(const float4*)(g_hbuf + (size_t)liA*FF + kb + aq*4);
            if (isW) rW = *(const float4*)(Wd + ((size_t)e*DD + n0 + grow)*FF + kb + gq*4);
        } else {
            rA = *(const float4*)(g_had + (size_t)liA*RR + aq*4);
            if (isW) rW = *(const float4*)(Bd + ((size_t)e*DD + n0 + grow)*RR + gq*4);
        }
    };
    auto sts_chunk = [&](int s) {
        sts_perm(&As[s][arow*16], aq, rA);
        if (isW) sts_perm(&Ws[s][grow*16], gq, rW);
    };

    float acc[2][2][4] = {};

    ldg_chunk(0); sts_chunk(0);
    ldg_chunk(1);
    __syncthreads();

    int r = lane & 3, rowq = lane >> 2;
    for (int kc = 0; kc < TCH; kc++) {
        int s = kc & 1;
        uint4 fa[2][2];
        #pragma unroll
        for (int mt = 0; mt < 2; mt++) {
            int rb = wm*32 + mt*16 + rowq;
            fa[mt][0] = *(const uint4*)&As[s][rb*16 + r*4];
            fa[mt][1] = *(const uint4*)&As[s][(rb+8)*16 + r*4];
        }
        #pragma unroll
        for (int nt = 0; nt < 2; nt++) {
            int nrow = wn*16 + nt*8 + rowq;
            uint4 fw = *(const uint4*)&Ws[s][nrow*16 + r*4];
            #pragma unroll
            for (int mt = 0; mt < 2; mt++) {
                uint32_t a0[4] = {fa[mt][0].x, fa[mt][1].x, fa[mt][0].y, fa[mt][1].y};
                uint32_t a1[4] = {fa[mt][0].z, fa[mt][1].z, fa[mt][0].w, fa[mt][1].w};
                mma8(acc[mt][nt], a0, fw.x, fw.y);
                mma8(acc[mt][nt], a1, fw.z, fw.w);
            }
        }
        if (kc + 1 < TCH) sts_chunk((kc + 1) & 1);
        if (kc + 2 < TCH) ldg_chunk(kc + 2);
        __syncthreads();
    }

    // epilogue: weighted write to slot scratch
    #pragma unroll
    for (int mt = 0; mt < 2; mt++) {
        #pragma unroll
        for (int half = 0; half < 2; half++) {
            int mrow = wm*32 + mt*16 + rowq + half*8;
            int m = m0 + mrow;
            if (m < n_e) {
                int tok = toks[mrow]; float w = wts[mrow]; int sl = slts[mrow];
                float* orow = g_scr + ((size_t)sl*SQ + tok)*DD + n0;
                #pragma unroll
                for (int nt = 0; nt < 2; nt++) {
                    int col = wn*16 + nt*8 + 2*r;
                    float2 v;
                    v.x = acc[mt][nt][half*2+0] * w;
                    v.y = acc[mt][nt][half*2+1] * w;
                    *(float2*)(orow + col) = v;
                }
            }
        }
    }
}

// ================= E5: slot combine =================
__global__ void e5_combine(float* __restrict__ out) {
    int i = blockIdx.x*blockDim.x + threadIdx.x;
    const float4* a = (const float4*)g_scr;
    const float4* b = (const float4*)(g_scr + (size_t)SQ*DD);
    float4 va = a[i], vb = b[i];
    ((float4*)out)[i] = make_float4(va.x+vb.x, va.y+vb.y, va.z+vb.z, va.w+vb.w);
}

// ================= launch =================
extern "C" void kernel_launch(void* const* d_in, const int* in_sizes, int n_in,
                              void* d_out, int out_size) {
    const float* x       = (const float*)d_in[0];
    const float* hist    = (const float*)d_in[1];
    const float* persona = (const float*)d_in[2];
    const float* fw1x    = (const float*)d_in[3];
    const float* fw1h    = (const float*)d_in[4];
    const float* fw1p    = (const float*)d_in[5];
    const float* fb1     = (const float*)d_in[6];
    const float* fw2     = (const float*)d_in[7];
    const float* fb2     = (const float*)d_in[8];
    const float* lng     = (const float*)d_in[9];
    const float* lnb     = (const float*)d_in[10];
    const float* gw      = (const float*)d_in[11];
    const float* gb      = (const float*)d_in[12];
    const float* Wg      = (const float*)d_in[13];
    const float* Wu      = (const float*)d_in[14];
    const float* Wd      = (const float*)d_in[15];
    const float* Ag      = (const float*)d_in[16];
    const float* Bg      = (const float*)d_in[17];
    const float* Au      = (const float*)d_in[18];
    const float* Bu      = (const float*)d_in[19];
    const float* Ad      = (const float*)d_in[20];
    const float* Bd      = (const float*)d_in[21];
    float* out = (float*)d_out;

    k0_hist_persona<<<1, 128>>>(hist, persona, fw1h, fw1p, lng, lnb, gw);
    k1t<<<dim3(2, 8), 256>>>(x, fw1x);
    k2b<<<dim3(SQ/8, EE), 256>>>(fb1, fw2, fb2, lng, gw, gb);
    k3_route<<<1, SQ>>>(out, out_size);
    e1_xa<<<dim3(SQ, EE), 128>>>(x, Ag, Au);
    e2_mma<<<dim3(4, FF/64, EE), 512>>>(x, Wg, Wu, Bg, Bu);
    e3_ha<<<dim3(SQ, EE), 128>>>(Ad);
    e4_mma<<<dim3(4, DD/64, EE), 512>>>(Wd, Bd);
    e5_combine<<<(SQ*DD)/(256*4), 256>>>(out);
}

// round 15
// speedup vs baseline: 1.2554x; 1.2554x over previous
#include <cuda_runtime.h>
#include <cstdint>
#include <math.h>

// Problem dims
#define SQ  512
#define DD  3072
#define DHH 256
#define EE  4
#define FF  8192
#define RR  16
#define H1N 128

// SIMT GEMM tiling (gating)
#define BK 16
#define LDP 68

// mma tiling
#define P2 20         // smem pitch in floats for K=16 chunks (+4 pad, conflict-free)

// ================= device scratch =================
__device__ float g_h1x[SQ*H1N];
__device__ float g_hh[H1N];
__device__ float g_hp[EE*H1N];
__device__ float g_cc[2];
__device__ float g_logits[EE*SQ];
__device__ int   g_cnt[EE];
__device__ int   g_tok[EE*SQ];
__device__ float g_wgt[EE*SQ];
__device__ int   g_slot[EE*SQ];
__device__ float g_xa[EE*SQ*32];          // 16 gate + 16 up LoRA x-projections
__device__ float g_had[EE*SQ*RR];         // down LoRA h-projection
__device__ float g_hbuf[(size_t)EE*SQ*FF];// silu(g)*u rows per (e, listpos)
__device__ float g_scr[2*SQ*DD];          // slot0/slot1 weighted expert outputs

// ================= mma helpers =================
__device__ __forceinline__ uint32_t f2tf32(float f) {
    uint32_t u;
    asm("cvt.rna.tf32.f32 %0, %1;" : "=r"(u) : "f"(f));
    return u;
}
__device__ __forceinline__ void sts_tf32x4(uint32_t* dst, float4 v) {
    uint4 o;
    o.x = f2tf32(v.x); o.y = f2tf32(v.y); o.z = f2tf32(v.z); o.w = f2tf32(v.w);
    *(uint4*)dst = o;
}
__device__ __forceinline__ void mma8(float* c, const uint32_t* a, uint32_t b0, uint32_t b1) {
    asm volatile(
        "mma.sync.aligned.m16n8k8.row.col.f32.tf32.tf32.f32 "
        "{%0,%1,%2,%3}, {%4,%5,%6,%7}, {%8,%9}, {%0,%1,%2,%3};"
        : "+f"(c[0]), "+f"(c[1]), "+f"(c[2]), "+f"(c[3])
        : "r"(a[0]), "r"(a[1]), "r"(a[2]), "r"(a[3]), "r"(b0), "r"(b1));
}

// ================= K0: history/persona projections + LN-fold constants =================
__global__ void k0_hist_persona(const float* __restrict__ hist,
                                const float* __restrict__ persona,
                                const float* __restrict__ fw1h,
                                const float* __restrict__ fw1p,
                                const float* __restrict__ lng,
                                const float* __restrict__ lnb,
                                const float* __restrict__ gw) {
    __shared__ float r3[128], r2[128];
    int k = threadIdx.x;  // 128
    float acc = 0.f;
    const float4* h4 = (const float4*)hist;
    const float4* w4 = (const float4*)(fw1h + (size_t)k*DHH);
    for (int i = 0; i < DHH/4; i++) {
        float4 a = h4[i], b = w4[i];
        acc += a.x*b.x + a.y*b.y + a.z*b.z + a.w*b.w;
    }
    g_hh[k] = acc;
    for (int e = 0; e < EE; e++) {
        const float4* p4 = (const float4*)(persona + (size_t)e*DD);
        const float4* q4 = (const float4*)(fw1p + (size_t)k*DD);
        float a2 = 0.f;
        for (int i = 0; i < DD/4; i++) {
            float4 a = p4[i], b = q4[i];
            a2 += a.x*b.x + a.y*b.y + a.z*b.z + a.w*b.w;
        }
        g_hp[e*H1N + k] = a2;
    }
    float c3 = 0.f, c2 = 0.f;
    for (int d = k; d < DD; d += 128) { c3 += lng[d]*gw[d]; c2 += lnb[d]*gw[d]; }
    r3[k] = c3; r2[k] = c2; __syncthreads();
    for (int o = 64; o > 0; o >>= 1) { if (k < o) { r3[k] += r3[k+o]; r2[k] += r2[k+o]; } __syncthreads(); }
    if (k == 0) { g_cc[0] = r3[0]; g_cc[1] = r2[0]; }
}

// ================= K1: tiled SGEMM  h1x[s,k] = x . fw1x^T =================
__global__ __launch_bounds__(256) void k1t(const float* __restrict__ x,
                                           const float* __restrict__ fw1x) {
    int n0 = blockIdx.x * 64, m0 = blockIdx.y * 64;
    __shared__ float Xs[BK][LDP], Ws[BK][LDP];
    int tid = threadIdx.x;
    int row = tid >> 2, qv = tid & 3, ty = tid >> 4, tx = tid & 15;
    const float* xp = x + (size_t)(m0+row)*DD + qv*4;
    const float* wp = fw1x + (size_t)(n0+row)*DD + qv*4;
    float acc[4][4] = {};
    for (int kk = 0; kk < DD; kk += BK) {
        float4 a = *(const float4*)(xp + kk);
        float4 b = *(const float4*)(wp + kk);
        __syncthreads();
        Xs[qv*4+0][row]=a.x; Xs[qv*4+1][row]=a.y; Xs[qv*4+2][row]=a.z; Xs[qv*4+3][row]=a.w;
        Ws[qv*4+0][row]=b.x; Ws[qv*4+1][row]=b.y; Ws[qv*4+2][row]=b.z; Ws[qv*4+3][row]=b.w;
        __syncthreads();
        #pragma unroll
        for (int k = 0; k < BK; k++) {
            float4 av = *(const float4*)&Xs[k][ty*4];
            float4 bv = *(const float4*)&Ws[k][tx*4];
            float am[4] = {av.x, av.y, av.z, av.w};
            float bm[4] = {bv.x, bv.y, bv.z, bv.w};
            #pragma unroll
            for (int i = 0; i < 4; i++)
                #pragma unroll
                for (int j = 0; j < 4; j++)
                    acc[i][j] += am[i]*bm[j];
        }
    }
    #pragma unroll
    for (int i = 0; i < 4; i++) {
        int m = m0 + ty*4 + i;
        *(float4*)(g_h1x + (size_t)m*H1N + n0 + tx*4) =
            make_float4(acc[i][0], acc[i][1], acc[i][2], acc[i][3]);
    }
}

// ================= K2: batched fused MLP -> LN-folded logit =================
__global__ __launch_bounds__(256) void k2b(const float* __restrict__ fb1,
                                           const float* __restrict__ fw2,
                                           const float* __restrict__ fb2,
                                           const float* __restrict__ lng,
                                           const float* __restrict__ gw,
                                           const float* __restrict__ gb) {
    int e = blockIdx.y;
    int s0 = blockIdx.x * 8;
    int tid = threadIdx.x;
    __shared__ float h1r[8][H1N];
    __shared__ float red[8][8][3];
    for (int i = tid; i < 8*H1N; i += 256) {
        int t = i >> 7, k = i & 127;
        float v = g_h1x[(size_t)(s0+t)*H1N + k] + g_hh[k] + fb1[k] + g_hp[e*H1N + k];
        h1r[t][k] = fmaxf(v, 0.f);
    }
    __syncthreads();
    float s1[8] = {}, s2[8] = {}, s3[8] = {};
    for (int i = 0; i < DD/256; i++) {
        int d = tid + i*256;
        const float4* wr = (const float4*)(fw2 + (size_t)d*H1N);
        float acc[8] = {};
        #pragma unroll 8
        for (int k4 = 0; k4 < H1N/4; k4++) {
            float4 b = wr[k4];
            #pragma unroll
            for (int t = 0; t < 8; t++) {
                float4 a = *(const float4*)&h1r[t][k4*4];
                acc[t] += a.x*b.x + a.y*b.y + a.z*b.z + a.w*b.w;
            }
        }
        float bias = fb2[d], c1 = lng[d]*gw[d];
        #pragma unroll
        for (int t = 0; t < 8; t++) {
            float f = fmaxf(acc[t] + bias, 0.f);
            s1[t] += f; s2[t] += f*f; s3[t] += f*c1;
        }
    }
    #pragma unroll
    for (int t = 0; t < 8; t++) {
        #pragma unroll
        for (int o = 16; o; o >>= 1) {
            s1[t] += __shfl_down_sync(~0u, s1[t], o);
            s2[t] += __shfl_down_sync(~0u, s2[t], o);
            s3[t] += __shfl_down_sync(~0u, s3[t], o);
        }
    }
    int wid = tid >> 5, lane = tid & 31;
    if (lane == 0) {
        #pragma unroll
        for (int t = 0; t < 8; t++) {
            red[wid][t][0] = s1[t]; red[wid][t][1] = s2[t]; red[wid][t][2] = s3[t];
        }
    }
    __syncthreads();
    if (tid < 8) {
        float a = 0.f, b = 0.f, c = 0.f;
        #pragma unroll
        for (int w = 0; w < 8; w++) { a += red[w][tid][0]; b += red[w][tid][1]; c += red[w][tid][2]; }
        float mean = a * (1.f/DD);
        float var  = b * (1.f/DD) - mean*mean;
        float rstd = rsqrtf(var + 1e-5f);
        g_logits[e*SQ + s0 + tid] = rstd*(c - mean*g_cc[0]) + g_cc[1] + gb[0];
    }
}

// ================= K3: softmax / top-2 / routing / entropy =================
__global__ void k3_route(float* __restrict__ d_out, int out_size) {
    int s = threadIdx.x;  // 512
    __shared__ float er[SQ];
    if (s < EE) g_cnt[s] = 0;
    __syncthreads();
    float l[EE];
    #pragma unroll
    for (int e = 0; e < EE; e++) l[e] = g_logits[e*SQ + s];
    float m = fmaxf(fmaxf(l[0], l[1]), fmaxf(l[2], l[3]));
    float p[EE]; float psum = 0.f;
    #pragma unroll
    for (int e = 0; e < EE; e++) { p[e] = expf(l[e]-m); psum += p[e]; }
    float inv = 1.f/psum;
    float ent = 0.f;
    #pragma unroll
    for (int e = 0; e < EE; e++) { p[e] *= inv; ent -= p[e]*logf(p[e] + 1e-9f); }
    int e0 = 0; float b0 = p[0];
    #pragma unroll
    for (int e = 1; e < EE; e++) if (p[e] > b0) { b0 = p[e]; e0 = e; }
    int e1 = -1; float b1 = -1.f;
    #pragma unroll
    for (int e = 0; e < EE; e++) if (e != e0 && p[e] > b1) { b1 = p[e]; e1 = e; }
    int i0 = atomicAdd(&g_cnt[e0], 1);
    g_tok[e0*SQ + i0] = s; g_wgt[e0*SQ + i0] = p[e0]; g_slot[e0*SQ + i0] = 0;
    int i1 = atomicAdd(&g_cnt[e1], 1);
    g_tok[e1*SQ + i1] = s; g_wgt[e1*SQ + i1] = p[e1]; g_slot[e1*SQ + i1] = 1;
    er[s] = ent; __syncthreads();
    for (int o = 256; o > 0; o >>= 1) { if (s < o) er[s] += er[s+o]; __syncthreads(); }
    if (s == 0 && out_size > SQ*DD) d_out[SQ*DD] = er[0] * (1.f/SQ);
}

// ================= E1: x LoRA projections (gate/up) =================
__global__ void e1_xa(const float* __restrict__ x,
                      const float* __restrict__ Ag,
                      const float* __restrict__ Au) {
    int e = blockIdx.y, i = blockIdx.x;
    if (i >= g_cnt[e]) return;
    int tok = g_tok[e*SQ + i];
    const float4* xr = (const float4*)(x + (size_t)tok*DD);
    int warp = threadIdx.x >> 5, lane = threadIdx.x & 31;
    for (int o = warp; o < 32; o += 4) {
        const float* A = (o < 16) ? Ag : Au;
        int r = o & 15;
        const float4* ar = (const float4*)(A + ((size_t)e*RR + r)*DD);
        float acc = 0.f;
        for (int qv = lane; qv < DD/4; qv += 32) {
            float4 a = xr[qv], b = ar[qv];
            acc += a.x*b.x + a.y*b.y + a.z*b.z + a.w*b.w;
        }
        #pragma unroll
        for (int off = 16; off; off >>= 1) acc += __shfl_down_sync(0xffffffffu, acc, off);
        if (lane == 0) g_xa[((size_t)e*SQ + i)*32 + o] = acc;
    }
}

// ================= E2: mma.sync tf32 gate+up GEMM + LoRA-as-K + SiLU =================
// Block tile 128(m) x 128(n), 512 threads = 16 warps (4m x 4n), warp tile 32x32.
// SINGLE-buffer static smem (30.7 KB, no opt-in needed); register-staged prefetch,
// 2 syncs/chunk (R7-proven pattern). K chunks of 16: 192 main + gate-LoRA + up-LoRA.
__global__ __launch_bounds__(512) void e2_mma(const float* __restrict__ x,
                                              const float* __restrict__ Wg,
                                              const float* __restrict__ Wu,
                                              const float* __restrict__ Bg,
                                              const float* __restrict__ Bu) {
    __shared__ uint32_t As[128*P2];
    __shared__ uint32_t Gs[128*P2];
    __shared__ uint32_t Us[128*P2];
    __shared__ int toks[128];
    int e = blockIdx.z;
    int n_e = g_cnt[e];
    int m0 = blockIdx.x * 128;
    if (m0 >= n_e) return;
    int n0 = blockIdx.y * 128;
    int tid = threadIdx.x, lane = tid & 31, wid = tid >> 5;
    int wm = wid >> 2, wn = wid & 3;
    if (tid < 128) toks[tid] = g_tok[e*SQ + min(m0 + tid, n_e - 1)];
    __syncthreads();

    const int NCH = DD/16;           // 192
    const int TCH = NCH + 2;         // + gate-LoRA + up-LoRA

    // loader slots: 512 threads = 128 rows x 4 quads, one float4 per tile each
    int arow = tid >> 2, aq = tid & 3;
    int liA = e*SQ + min(m0 + arow, n_e - 1);

    float4 ra, rg, ru;
    auto load_chunk = [&](int kc) {
        if (kc < NCH) {
            int kb = kc*16;
            ra = *(const float4*)(x + (size_t)toks[arow]*DD + kb + aq*4);
            size_t wo = ((size_t)e*FF + n0 + arow)*DD + kb + aq*4;
            rg = *(const float4*)(Wg + wo);
            ru = *(const float4*)(Wu + wo);
        } else {
            int off = (kc == NCH) ? 0 : 16;  // gate cols 0-15, up cols 16-31
            ra = *(const float4*)(g_xa + (size_t)liA*32 + off + aq*4);
            size_t bo = ((size_t)e*FF + n0 + arow)*RR + aq*4;
            if (kc == NCH) rg = *(const float4*)(Bg + bo);
            else           ru = *(const float4*)(Bu + bo);
        }
    };
    auto store_chunk = [&](int kc) {
        sts_tf32x4(&As[arow*P2 + aq*4], ra);
        if (kc != NCH+1) sts_tf32x4(&Gs[arow*P2 + aq*4], rg);
        if (kc != NCH)   sts_tf32x4(&Us[arow*P2 + aq*4], ru);
    };

    float accg[2][4][4] = {}, accu[2][4][4] = {};

    load_chunk(0);
    store_chunk(0);
    __syncthreads();

    for (int kc = 0; kc < TCH; kc++) {
        if (kc + 1 < TCH) load_chunk(kc + 1);     // LDG into regs, covered by compute
        bool dog = (kc != NCH+1), dou = (kc != NCH);
        #pragma unroll
        for (int ks = 0; ks < 2; ks++) {
            int kb = ks*8 + (lane & 3);
            uint32_t a[2][4];
            #pragma unroll
            for (int mt = 0; mt < 2; mt++) {
                const uint32_t* ap = &As[(wm*32 + mt*16 + (lane >> 2))*P2 + kb];
                a[mt][0] = ap[0];     a[mt][2] = ap[4];
                a[mt][1] = ap[8*P2];  a[mt][3] = ap[8*P2 + 4];
            }
            #pragma unroll
            for (int nt = 0; nt < 4; nt++) {
                const uint32_t* gp = &Gs[(wn*32 + nt*8 + (lane >> 2))*P2 + kb];
                const uint32_t* up = &Us[(wn*32 + nt*8 + (lane >> 2))*P2 + kb];
                uint32_t g0 = 0, g1 = 0, u0 = 0, u1 = 0;
                if (dog) { g0 = gp[0]; g1 = gp[4]; }
                if (dou) { u0 = up[0]; u1 = up[4]; }
                #pragma unroll
                for (int mt = 0; mt < 2; mt++) {
                    if (dog) mma8(accg[mt][nt], a[mt], g0, g1);
                    if (dou) mma8(accu[mt][nt], a[mt], u0, u1);
                }
            }
        }
        if (kc + 1 < TCH) {
            __syncthreads();                       // all compute on this chunk done
            store_chunk(kc + 1);                   // overwrite single buffer
            __syncthreads();
        }
    }

    // epilogue: silu(g)*u -> g_hbuf
    #pragma unroll
    for (int mt = 0; mt < 2; mt++) {
        #pragma unroll
        for (int half = 0; half < 2; half++) {
            int mrow = wm*32 + mt*16 + (lane >> 2) + half*8;
            int m = m0 + mrow;
            if (m < n_e) {
                float* hr = g_hbuf + ((size_t)e*SQ + m)*FF + n0;
                #pragma unroll
                for (int nt = 0; nt < 4; nt++) {
                    int col = wn*32 + nt*8 + 2*(lane & 3);
                    float gg0 = accg[mt][nt][half*2+0], uu0 = accu[mt][nt][half*2+0];
                    float gg1 = accg[mt][nt][half*2+1], uu1 = accu[mt][nt][half*2+1];
                    float2 hv;
                    hv.x = gg0*uu0/(1.f + __expf(-gg0));
                    hv.y = gg1*uu1/(1.f + __expf(-gg1));
                    *(float2*)(hr + col) = hv;
                }
            }
        }
    }
}

// ================= E3: h LoRA projection (down) =================
__global__ void e3_ha(const float* __restrict__ Ad) {
    int e = blockIdx.y, i = blockIdx.x;
    if (i >= g_cnt[e]) return;
    const float4* hr = (const float4*)(g_hbuf + ((size_t)e*SQ + i)*FF);
    int warp = threadIdx.x >> 5, lane = threadIdx.x & 31;
    for (int r = warp; r < RR; r += 4) {
        const float4* ar = (const float4*)(Ad + ((size_t)e*RR + r)*FF);
        float acc = 0.f;
        for (int qv = lane; qv < FF/4; qv += 32) {
            float4 a = hr[qv], b = ar[qv];
            acc += a.x*b.x + a.y*b.y + a.z*b.z + a.w*b.w;
        }
        #pragma unroll
        for (int off = 16; off; off >>= 1) acc += __shfl_down_sync(0xffffffffu, acc, off);
        if (lane == 0) g_had[((size_t)e*SQ + i)*RR + r] = acc;
    }
}

// ================= E4: mma.sync tf32 down GEMM + LoRA-as-K + weighted slot write =================
// Block tile 128(m) x 128(n of D), 512 threads, warp tile 32x32.
// SINGLE-buffer static smem (20.5 KB). K chunks of 16: 512 main + 1 LoRA.
__global__ __launch_bounds__(512) void e4_mma(const float* __restrict__ Wd,
                                              const float* __restrict__ Bd) {
    __shared__ uint32_t As[128*P2];
    __shared__ uint32_t Ws[128*P2];
    __shared__ int   toks[128];
    __shared__ float wts[128];
    __shared__ int   slts[128];
    int e = blockIdx.z;
    int n_e = g_cnt[e];
    int m0 = blockIdx.x * 128;
    if (m0 >= n_e) return;
    int n0 = blockIdx.y * 128;
    int tid = threadIdx.x, lane = tid & 31, wid = tid >> 5;
    int wm = wid >> 2, wn = wid & 3;
    if (tid < 128) {
        int li = e*SQ + min(m0 + tid, n_e - 1);
        toks[tid] = g_tok[li]; wts[tid] = g_wgt[li]; slts[tid] = g_slot[li];
    }
    __syncthreads();

    const int NCH = FF/16;           // 512
    const int TCH = NCH + 1;

    int arow = tid >> 2, aq = tid & 3;
    int liA = e*SQ + min(m0 + arow, n_e - 1);

    float4 ra, rw;
    auto load_chunk = [&](int kc) {
        if (kc < NCH) {
            int kb = kc*16;
            ra = *(const float4*)(g_hbuf + (size_t)liA*FF + kb + aq*4);
            rw = *(const float4*)(Wd + ((size_t)e*DD + n0 + arow)*FF + kb + aq*4);
        } else {
            ra = *(const float4*)(g_had + (size_t)liA*RR + aq*4);
            rw = *(const float4*)(Bd + ((size_t)e*DD + n0 + arow)*RR + aq*4);
        }
    };
    auto store_chunk = [&]() {
        sts_tf32x4(&As[arow*P2 + aq*4], ra);
        sts_tf32x4(&Ws[arow*P2 + aq*4], rw);
    };

    float acc[2][4][4] = {};

    load_chunk(0);
    store_chunk();
    __syncthreads();

    for (int kc = 0; kc < TCH; kc++) {
        if (kc + 1 < TCH) load_chunk(kc + 1);
        #pragma unroll
        for (int ks = 0; ks < 2; ks++) {
            int kb = ks*8 + (lane & 3);
            uint32_t a[2][4];
            #pragma unroll
            for (int mt = 0; mt < 2; mt++) {
                const uint32_t* ap = &As[(wm*32 + mt*16 + (lane >> 2))*P2 + kb];
                a[mt][0] = ap[0];     a[mt][2] = ap[4];
                a[mt][1] = ap[8*P2];  a[mt][3] = ap[8*P2 + 4];
            }
            #pragma unroll
            for (int nt = 0; nt < 4; nt++) {
                const uint32_t* wp = &Ws[(wn*32 + nt*8 + (lane >> 2))*P2 + kb];
                uint32_t w0 = wp[0], w1 = wp[4];
                #pragma unroll
                for (int mt = 0; mt < 2; mt++)
                    mma8(acc[mt][nt], a[mt], w0, w1);
            }
        }
        if (kc + 1 < TCH) {
            __syncthreads();
            store_chunk();
            __syncthreads();
        }
    }

    // epilogue: weighted write to slot scratch
    #pragma unroll
    for (int mt = 0; mt < 2; mt++) {
        #pragma unroll
        for (int half = 0; half < 2; half++) {
            int mrow = wm*32 + mt*16 + (lane >> 2) + half*8;
            int m = m0 + mrow;
            if (m < n_e) {
                int tok = toks[mrow]; float w = wts[mrow]; int sl = slts[mrow];
                float* orow = g_scr + ((size_t)sl*SQ + tok)*DD + n0;
                #pragma unroll
                for (int nt = 0; nt < 4; nt++) {
                    int col = wn*32 + nt*8 + 2*(lane & 3);
                    float2 v;
                    v.x = acc[mt][nt][half*2+0] * w;
                    v.y = acc[mt][nt][half*2+1] * w;
                    *(float2*)(orow + col) = v;
                }
            }
        }
    }
}

// ================= E5: slot combine =================
__global__ void e5_combine(float* __restrict__ out) {
    int i = blockIdx.x*blockDim.x + threadIdx.x;
    const float4* a = (const float4*)g_scr;
    const float4* b = (const float4*)(g_scr + (size_t)SQ*DD);
    float4 va = a[i], vb = b[i];
    ((float4*)out)[i] = make_float4(va.x+vb.x, va.y+vb.y, va.z+vb.z, va.w+vb.w);
}

// ================= launch =================
extern "C" void kernel_launch(void* const* d_in, const int* in_sizes, int n_in,
                              void* d_out, int out_size) {
    const float* x       = (const float*)d_in[0];
    const float* hist    = (const float*)d_in[1];
    const float* persona = (const float*)d_in[2];
    const float* fw1x    = (const float*)d_in[3];
    const float* fw1h    = (const float*)d_in[4];
    const float* fw1p    = (const float*)d_in[5];
    const float* fb1     = (const float*)d_in[6];
    const float* fw2     = (const float*)d_in[7];
    const float* fb2     = (const float*)d_in[8];
    const float* lng     = (const float*)d_in[9];
    const float* lnb     = (const float*)d_in[10];
    const float* gw      = (const float*)d_in[11];
    const float* gb      = (const float*)d_in[12];
    const float* Wg      = (const float*)d_in[13];
    const float* Wu      = (const float*)d_in[14];
    const float* Wd      = (const float*)d_in[15];
    const float* Ag      = (const float*)d_in[16];
    const float* Bg      = (const float*)d_in[17];
    const float* Au      = (const float*)d_in[18];
    const float* Bu      = (const float*)d_in[19];
    const float* Ad      = (const float*)d_in[20];
    const float* Bd      = (const float*)d_in[21];
    float* out = (float*)d_out;

    k0_hist_persona<<<1, 128>>>(hist, persona, fw1h, fw1p, lng, lnb, gw);
    k1t<<<dim3(2, 8), 256>>>(x, fw1x);
    k2b<<<dim3(SQ/8, EE), 256>>>(fb1, fw2, fb2, lng, gw, gb);
    k3_route<<<1, SQ>>>(out, out_size);
    e1_xa<<<dim3(SQ, EE), 128>>>(x, Ag, Au);
    e2_mma<<<dim3(4, FF/128, EE), 512>>>(x, Wg, Wu, Bg, Bu);
    e3_ha<<<dim3(SQ, EE), 128>>>(Ad);
    e4_mma<<<dim3(4, DD/128, EE), 512>>>(Wd, Bd);
    e5_combine<<<(SQ*DD)/(256*4), 256>>>(out);
}

// round 16
// speedup vs baseline: 1.3057x; 1.0401x over previous
#include <cuda_runtime.h>
#include <cstdint>
#include <math.h>

// Problem dims
#define SQ  512
#define DD  3072
#define DHH 256
#define EE  4
#define FF  8192
#define RR  16
#define H1N 128

// SIMT GEMM tiling (gating)
#define BK 16
#define LDP 68

// mma tiling
#define P2 20         // smem pitch in floats for K=16 chunks (+4 pad, conflict-free)

// ================= device scratch =================
__device__ float g_h1x[SQ*H1N];
__device__ float g_hh[H1N];
__device__ float g_hp[EE*H1N];
__device__ float g_cc[2];
__device__ float g_logits[EE*SQ];
__device__ int   g_cnt[EE];
__device__ int   g_tok[EE*SQ];
__device__ float g_wgt[EE*SQ];
__device__ int   g_slot[EE*SQ];
__device__ float g_xa[EE*SQ*32];          // 16 gate + 16 up LoRA x-projections
__device__ float g_had[EE*SQ*RR];         // down LoRA h-projection
__device__ float g_hbuf[(size_t)EE*SQ*FF];// silu(g)*u rows per (e, listpos)
__device__ float g_scr[2*SQ*DD];          // slot0/slot1 weighted expert outputs

// ================= mma helpers =================
__device__ __forceinline__ uint32_t f2tf32(float f) {
    uint32_t u;
    asm("cvt.rna.tf32.f32 %0, %1;" : "=r"(u) : "f"(f));
    return u;
}
__device__ __forceinline__ void sts_tf32x4(uint32_t* dst, float4 v) {
    uint4 o;
    o.x = f2tf32(v.x); o.y = f2tf32(v.y); o.z = f2tf32(v.z); o.w = f2tf32(v.w);
    *(uint4*)dst = o;
}
__device__ __forceinline__ void mma8(float* c, const uint32_t* a, uint32_t b0, uint32_t b1) {
    asm volatile(
        "mma.sync.aligned.m16n8k8.row.col.f32.tf32.tf32.f32 "
        "{%0,%1,%2,%3}, {%4,%5,%6,%7}, {%8,%9}, {%0,%1,%2,%3};"
        : "+f"(c[0]), "+f"(c[1]), "+f"(c[2]), "+f"(c[3])
        : "r"(a[0]), "r"(a[1]), "r"(a[2]), "r"(a[3]), "r"(b0), "r"(b1));
}

// ================= K0: history/persona projections + LN-fold constants =================
__global__ void k0_hist_persona(const float* __restrict__ hist,
                                const float* __restrict__ persona,
                                const float* __restrict__ fw1h,
                                const float* __restrict__ fw1p,
                                const float* __restrict__ lng,
                                const float* __restrict__ lnb,
                                const float* __restrict__ gw) {
    __shared__ float r3[128], r2[128];
    int k = threadIdx.x;  // 128
    float acc = 0.f;
    const float4* h4 = (const float4*)hist;
    const float4* w4 = (const float4*)(fw1h + (size_t)k*DHH);
    for (int i = 0; i < DHH/4; i++) {
        float4 a = h4[i], b = w4[i];
        acc += a.x*b.x + a.y*b.y + a.z*b.z + a.w*b.w;
    }
    g_hh[k] = acc;
    for (int e = 0; e < EE; e++) {
        const float4* p4 = (const float4*)(persona + (size_t)e*DD);
        const float4* q4 = (const float4*)(fw1p + (size_t)k*DD);
        float a2 = 0.f;
        for (int i = 0; i < DD/4; i++) {
            float4 a = p4[i], b = q4[i];
            a2 += a.x*b.x + a.y*b.y + a.z*b.z + a.w*b.w;
        }
        g_hp[e*H1N + k] = a2;
    }
    float c3 = 0.f, c2 = 0.f;
    for (int d = k; d < DD; d += 128) { c3 += lng[d]*gw[d]; c2 += lnb[d]*gw[d]; }
    r3[k] = c3; r2[k] = c2; __syncthreads();
    for (int o = 64; o > 0; o >>= 1) { if (k < o) { r3[k] += r3[k+o]; r2[k] += r2[k+o]; } __syncthreads(); }
    if (k == 0) { g_cc[0] = r3[0]; g_cc[1] = r2[0]; }
}

// ================= K1: tiled SGEMM  h1x[s,k] = x . fw1x^T =================
__global__ __launch_bounds__(256) void k1t(const float* __restrict__ x,
                                           const float* __restrict__ fw1x) {
    int n0 = blockIdx.x * 64, m0 = blockIdx.y * 64;
    __shared__ float Xs[BK][LDP], Ws[BK][LDP];
    int tid = threadIdx.x;
    int row = tid >> 2, qv = tid & 3, ty = tid >> 4, tx = tid & 15;
    const float* xp = x + (size_t)(m0+row)*DD + qv*4;
    const float* wp = fw1x + (size_t)(n0+row)*DD + qv*4;
    float acc[4][4] = {};
    for (int kk = 0; kk < DD; kk += BK) {
        float4 a = *(const float4*)(xp + kk);
        float4 b = *(const float4*)(wp + kk);
        __syncthreads();
        Xs[qv*4+0][row]=a.x; Xs[qv*4+1][row]=a.y; Xs[qv*4+2][row]=a.z; Xs[qv*4+3][row]=a.w;
        Ws[qv*4+0][row]=b.x; Ws[qv*4+1][row]=b.y; Ws[qv*4+2][row]=b.z; Ws[qv*4+3][row]=b.w;
        __syncthreads();
        #pragma unroll
        for (int k = 0; k < BK; k++) {
            float4 av = *(const float4*)&Xs[k][ty*4];
            float4 bv = *(const float4*)&Ws[k][tx*4];
            float am[4] = {av.x, av.y, av.z, av.w};
            float bm[4] = {bv.x, bv.y, bv.z, bv.w};
            #pragma unroll
            for (int i = 0; i < 4; i++)
                #pragma unroll
                for (int j = 0; j < 4; j++)
                    acc[i][j] += am[i]*bm[j];
        }
    }
    #pragma unroll
    for (int i = 0; i < 4; i++) {
        int m = m0 + ty*4 + i;
        *(float4*)(g_h1x + (size_t)m*H1N + n0 + tx*4) =
            make_float4(acc[i][0], acc[i][1], acc[i][2], acc[i][3]);
    }
}

// ================= K2: batched fused MLP -> LN-folded logit =================
__global__ __launch_bounds__(256) void k2b(const float* __restrict__ fb1,
                                           const float* __restrict__ fw2,
                                           const float* __restrict__ fb2,
                                           const float* __restrict__ lng,
                                           const float* __restrict__ gw,
                                           const float* __restrict__ gb) {
    int e = blockIdx.y;
    int s0 = blockIdx.x * 8;
    int tid = threadIdx.x;
    __shared__ float h1r[8][H1N];
    __shared__ float red[8][8][3];
    for (int i = tid; i < 8*H1N; i += 256) {
        int t = i >> 7, k = i & 127;
        float v = g_h1x[(size_t)(s0+t)*H1N + k] + g_hh[k] + fb1[k] + g_hp[e*H1N + k];
        h1r[t][k] = fmaxf(v, 0.f);
    }
    __syncthreads();
    float s1[8] = {}, s2[8] = {}, s3[8] = {};
    for (int i = 0; i < DD/256; i++) {
        int d = tid + i*256;
        const float4* wr = (const float4*)(fw2 + (size_t)d*H1N);
        float acc[8] = {};
        #pragma unroll 8
        for (int k4 = 0; k4 < H1N/4; k4++) {
            float4 b = wr[k4];
            #pragma unroll
            for (int t = 0; t < 8; t++) {
                float4 a = *(const float4*)&h1r[t][k4*4];
                acc[t] += a.x*b.x + a.y*b.y + a.z*b.z + a.w*b.w;
            }
        }
        float bias = fb2[d], c1 = lng[d]*gw[d];
        #pragma unroll
        for (int t = 0; t < 8; t++) {
            float f = fmaxf(acc[t] + bias, 0.f);
            s1[t] += f; s2[t] += f*f; s3[t] += f*c1;
        }
    }
    #pragma unroll
    for (int t = 0; t < 8; t++) {
        #pragma unroll
        for (int o = 16; o; o >>= 1) {
            s1[t] += __shfl_down_sync(~0u, s1[t], o);
            s2[t] += __shfl_down_sync(~0u, s2[t], o);
            s3[t] += __shfl_down_sync(~0u, s3[t], o);
        }
    }
    int wid = tid >> 5, lane = tid & 31;
    if (lane == 0) {
        #pragma unroll
        for (int t = 0; t < 8; t++) {
            red[wid][t][0] = s1[t]; red[wid][t][1] = s2[t]; red[wid][t][2] = s3[t];
        }
    }
    __syncthreads();
    if (tid < 8) {
        float a = 0.f, b = 0.f, c = 0.f;
        #pragma unroll
        for (int w = 0; w < 8; w++) { a += red[w][tid][0]; b += red[w][tid][1]; c += red[w][tid][2]; }
        float mean = a * (1.f/DD);
        float var  = b * (1.f/DD) - mean*mean;
        float rstd = rsqrtf(var + 1e-5f);
        g_logits[e*SQ + s0 + tid] = rstd*(c - mean*g_cc[0]) + g_cc[1] + gb[0];
    }
}

// ================= K3: softmax / top-2 / routing / entropy =================
__global__ void k3_route(float* __restrict__ d_out, int out_size) {
    int s = threadIdx.x;  // 512
    __shared__ float er[SQ];
    if (s < EE) g_cnt[s] = 0;
    __syncthreads();
    float l[EE];
    #pragma unroll
    for (int e = 0; e < EE; e++) l[e] = g_logits[e*SQ + s];
    float m = fmaxf(fmaxf(l[0], l[1]), fmaxf(l[2], l[3]));
    float p[EE]; float psum = 0.f;
    #pragma unroll
    for (int e = 0; e < EE; e++) { p[e] = expf(l[e]-m); psum += p[e]; }
    float inv = 1.f/psum;
    float ent = 0.f;
    #pragma unroll
    for (int e = 0; e < EE; e++) { p[e] *= inv; ent -= p[e]*logf(p[e] + 1e-9f); }
    int e0 = 0; float b0 = p[0];
    #pragma unroll
    for (int e = 1; e < EE; e++) if (p[e] > b0) { b0 = p[e]; e0 = e; }
    int e1 = -1; float b1 = -1.f;
    #pragma unroll
    for (int e = 0; e < EE; e++) if (e != e0 && p[e] > b1) { b1 = p[e]; e1 = e; }
    int i0 = atomicAdd(&g_cnt[e0], 1);
    g_tok[e0*SQ + i0] = s; g_wgt[e0*SQ + i0] = p[e0]; g_slot[e0*SQ + i0] = 0;
    int i1 = atomicAdd(&g_cnt[e1], 1);
    g_tok[e1*SQ + i1] = s; g_wgt[e1*SQ + i1] = p[e1]; g_slot[e1*SQ + i1] = 1;
    er[s] = ent; __syncthreads();
    for (int o = 256; o > 0; o >>= 1) { if (s < o) er[s] += er[s+o]; __syncthreads(); }
    if (s == 0 && out_size > SQ*DD) d_out[SQ*DD] = er[0] * (1.f/SQ);
}

// ================= E1: x LoRA projections (gate/up) =================
__global__ void e1_xa(const float* __restrict__ x,
                      const float* __restrict__ Ag,
                      const float* __restrict__ Au) {
    int e = blockIdx.y, i = blockIdx.x;
    if (i >= g_cnt[e]) return;
    int tok = g_tok[e*SQ + i];
    const float4* xr = (const float4*)(x + (size_t)tok*DD);
    int warp = threadIdx.x >> 5, lane = threadIdx.x & 31;
    for (int o = warp; o < 32; o += 4) {
        const float* A = (o < 16) ? Ag : Au;
        int r = o & 15;
        const float4* ar = (const float4*)(A + ((size_t)e*RR + r)*DD);
        float acc = 0.f;
        for (int qv = lane; qv < DD/4; qv += 32) {
            float4 a = xr[qv], b = ar[qv];
            acc += a.x*b.x + a.y*b.y + a.z*b.z + a.w*b.w;
        }
        #pragma unroll
        for (int off = 16; off; off >>= 1) acc += __shfl_down_sync(0xffffffffu, acc, off);
        if (lane == 0) g_xa[((size_t)e*SQ + i)*32 + o] = acc;
    }
}

// ================= E2: mma.sync tf32 gate+up GEMM, 2-deep weight prefetch =================
// R7 geometry: block 128(m) x 64(n), 256 threads = 8 warps (2m x 4n), warp tile 64x16,
// 2-stage smem double buffer (40 KB static), pitch-20 conflict-free layout.
// NEW: weight LDGs issued 2 chunks ahead into alternating named register sets.
// K chunks of 16: DD/16 = 192 main + chunk 192 (gate LoRA) + 193 (up LoRA).
__global__ __launch_bounds__(256, 2) void e2_mma(const float* __restrict__ x,
                                                 const float* __restrict__ Wg,
                                                 const float* __restrict__ Wu,
                                                 const float* __restrict__ Bg,
                                                 const float* __restrict__ Bu) {
    int e = blockIdx.z;
    int n_e = g_cnt[e];
    int m0 = blockIdx.x * 128;
    if (m0 >= n_e) return;
    int n0 = blockIdx.y * 64;
    __shared__ uint32_t As[2][128*P2];
    __shared__ uint32_t Gs[2][64*P2];
    __shared__ uint32_t Us[2][64*P2];
    __shared__ int toks[128];
    int tid = threadIdx.x, lane = tid & 31, wid = tid >> 5;
    int wm = wid >> 2, wn = wid & 3;
    if (tid < 128) toks[tid] = g_tok[e*SQ + min(m0 + tid, n_e - 1)];
    __syncthreads();

    const int NCH = DD/16;           // 192
    const int TCH = NCH + 2;         // + gate-LoRA + up-LoRA

    int ar0 = tid >> 2, akq = tid & 3;      // A rows ar0, ar0+64
    int gr = tid >> 2, gkq = tid & 3;       // G/U: 64 rows x 4 quads
    int li0 = e*SQ + min(m0 + ar0, n_e - 1);
    int li1 = e*SQ + min(m0 + ar0 + 64, n_e - 1);

    float4 ra0, ra1;                 // A staging (1-deep; x / g_xa are L2-hot)
    float4 rg0, ru0, rg1, ru1;       // weight staging (2-deep, named sets)

    auto ldA = [&](int kc) {
        if (kc < NCH) {
            int kb = kc*16;
            ra0 = *(const float4*)(x + (size_t)toks[ar0]*DD    + kb + akq*4);
            ra1 = *(const float4*)(x + (size_t)toks[ar0+64]*DD + kb + akq*4);
        } else {
            int off = (kc == NCH) ? 0 : 16;
            ra0 = *(const float4*)(g_xa + (size_t)li0*32 + off + akq*4);
            ra1 = *(const float4*)(g_xa + (size_t)li1*32 + off + akq*4);
        }
    };
    auto ldW0 = [&](int kc) {
        if (kc < NCH) {
            size_t wo = ((size_t)e*FF + n0 + gr)*DD + kc*16 + gkq*4;
            rg0 = *(const float4*)(Wg + wo);
            ru0 = *(const float4*)(Wu + wo);
        } else if (kc == NCH) {
            rg0 = *(const float4*)(Bg + ((size_t)e*FF + n0 + gr)*RR + gkq*4);
        } else {
            ru0 = *(const float4*)(Bu + ((size_t)e*FF + n0 + gr)*RR + gkq*4);
        }
    };
    auto ldW1 = [&](int kc) {
        if (kc < NCH) {
            size_t wo = ((size_t)e*FF + n0 + gr)*DD + kc*16 + gkq*4;
            rg1 = *(const float4*)(Wg + wo);
            ru1 = *(const float4*)(Wu + wo);
        } else if (kc == NCH) {
            rg1 = *(const float4*)(Bg + ((size_t)e*FF + n0 + gr)*RR + gkq*4);
        } else {
            ru1 = *(const float4*)(Bu + ((size_t)e*FF + n0 + gr)*RR + gkq*4);
        }
    };
    auto sts0 = [&](int s, int kc) {           // store from set0
        sts_tf32x4(&As[s][ ar0*P2     + akq*4], ra0);
        sts_tf32x4(&As[s][(ar0+64)*P2 + akq*4], ra1);
        if (kc != NCH+1) sts_tf32x4(&Gs[s][gr*P2 + gkq*4], rg0);
        if (kc != NCH)   sts_tf32x4(&Us[s][gr*P2 + gkq*4], ru0);
    };
    auto sts1 = [&](int s, int kc) {           // store from set1
        sts_tf32x4(&As[s][ ar0*P2     + akq*4], ra0);
        sts_tf32x4(&As[s][(ar0+64)*P2 + akq*4], ra1);
        if (kc != NCH+1) sts_tf32x4(&Gs[s][gr*P2 + gkq*4], rg1);
        if (kc != NCH)   sts_tf32x4(&Us[s][gr*P2 + gkq*4], ru1);
    };

    float accg[4][2][4] = {}, accu[4][2][4] = {};

    auto compute = [&](int s, bool dog, bool dou) {
        #pragma unroll
        for (int ks = 0; ks < 2; ks++) {
            int kb = ks*8 + (lane & 3);
            uint32_t a[4][4];
            #pragma unroll
            for (int mt = 0; mt < 4; mt++) {
                const uint32_t* ap = &As[s][(wm*64 + mt*16 + (lane >> 2))*P2 + kb];
                a[mt][0] = ap[0];     a[mt][2] = ap[4];
                a[mt][1] = ap[8*P2];  a[mt][3] = ap[8*P2 + 4];
            }
            #pragma unroll
            for (int nt = 0; nt < 2; nt++) {
                const uint32_t* gp = &Gs[s][(wn*16 + nt*8 + (lane >> 2))*P2 + kb];
                const uint32_t* up = &Us[s][(wn*16 + nt*8 + (lane >> 2))*P2 + kb];
                uint32_t g0 = 0, g1 = 0, u0 = 0, u1 = 0;
                if (dog) { g0 = gp[0]; g1 = gp[4]; }
                if (dou) { u0 = up[0]; u1 = up[4]; }
                #pragma unroll
                for (int mt = 0; mt < 4; mt++) {
                    if (dog) mma8(accg[mt][nt], a[mt], g0, g1);
                    if (dou) mma8(accu[mt][nt], a[mt], u0, u1);
                }
            }
        }
    };

    // prologue: W(0)->set0, A(0), STS chunk0 -> stage0; W(1)->set1
    ldW0(0); ldA(0);
    sts0(0, 0);
    ldW1(1);
    __syncthreads();

    for (int kc = 0; kc < TCH; kc += 2) {
        // even chunk kc: stage0, weights already in smem; set0 free
        if (kc + 1 < TCH) ldA(kc + 1);
        if (kc + 2 < TCH) ldW0(kc + 2);
        compute(0, kc != NCH+1, kc != NCH);
        if (kc + 1 < TCH) {
            __syncthreads();
            sts1(1, kc + 1);
            __syncthreads();
        }
        // odd chunk kc+1: stage1; set1 free
        if (kc + 1 < TCH) {
            if (kc + 2 < TCH) ldA(kc + 2);
            if (kc + 3 < TCH) ldW1(kc + 3);
            compute(1, (kc+1) != NCH+1, (kc+1) != NCH);
            if (kc + 2 < TCH) {
                __syncthreads();
                sts0(0, kc + 2);
                __syncthreads();
            }
        }
    }

    // epilogue: silu(g)*u -> g_hbuf
    #pragma unroll
    for (int mt = 0; mt < 4; mt++) {
        #pragma unroll
        for (int half = 0; half < 2; half++) {
            int mrow = wm*64 + mt*16 + (lane >> 2) + half*8;
            int m = m0 + mrow;
            if (m < n_e) {
                float* hr = g_hbuf + ((size_t)e*SQ + m)*FF + n0;
                #pragma unroll
                for (int nt = 0; nt < 2; nt++) {
                    int col = wn*16 + nt*8 + 2*(lane & 3);
                    float gg0 = accg[mt][nt][half*2+0], uu0 = accu[mt][nt][half*2+0];
                    float gg1 = accg[mt][nt][half*2+1], uu1 = accu[mt][nt][half*2+1];
                    float2 hv;
                    hv.x = gg0*uu0/(1.f + __expf(-gg0));
                    hv.y = gg1*uu1/(1.f + __expf(-gg1));
                    *(float2*)(hr + col) = hv;
                }
            }
        }
    }
}

// ================= E3: h LoRA projection (down) =================
__global__ void e3_ha(const float* __restrict__ Ad) {
    int e = blockIdx.y, i = blockIdx.x;
    if (i >= g_cnt[e]) return;
    const float4* hr = (const float4*)(g_hbuf + ((size_t)e*SQ + i)*FF);
    int warp = threadIdx.x >> 5, lane = threadIdx.x & 31;
    for (int r = warp; r < RR; r += 4) {
        const float4* ar = (const float4*)(Ad + ((size_t)e*RR + r)*FF);
        float acc = 0.f;
        for (int qv = lane; qv < FF/4; qv += 32) {
            float4 a = hr[qv], b = ar[qv];
            acc += a.x*b.x + a.y*b.y + a.z*b.z + a.w*b.w;
        }
        #pragma unroll
        for (int off = 16; off; off >>= 1) acc += __shfl_down_sync(0xffffffffu, acc, off);
        if (lane == 0) g_had[((size_t)e*SQ + i)*RR + r] = acc;
    }
}

// ================= E4: mma.sync tf32 down GEMM, 2-deep weight prefetch =================
// R7 geometry: block 128(m) x 64(n), 256 threads, warp tile 64x16, 2-stage smem.
// K chunks of 16: FF/16 = 512 main + 1 LoRA.
__global__ __launch_bounds__(256, 2) void e4_mma(const float* __restrict__ Wd,
                                                 const float* __restrict__ Bd) {
    int e = blockIdx.z;
    int n_e = g_cnt[e];
    int m0 = blockIdx.x * 128;
    if (m0 >= n_e) return;
    int n0 = blockIdx.y * 64;
    __shared__ uint32_t As[2][128*P2];
    __shared__ uint32_t Ws[2][64*P2];
    __shared__ int   toks[128];
    __shared__ float wts[128];
    __shared__ int   slts[128];
    int tid = threadIdx.x, lane = tid & 31, wid = tid >> 5;
    int wm = wid >> 2, wn = wid & 3;
    if (tid < 128) {
        int li = e*SQ + min(m0 + tid, n_e - 1);
        toks[tid] = g_tok[li]; wts[tid] = g_wgt[li]; slts[tid] = g_slot[li];
    }
    __syncthreads();

    const int NCH = FF/16;           // 512
    const int TCH = NCH + 1;

    int ar0 = tid >> 2, akq = tid & 3;
    int gr = tid >> 2, gkq = tid & 3;
    int li0 = e*SQ + min(m0 + ar0, n_e - 1);
    int li1 = e*SQ + min(m0 + ar0 + 64, n_e - 1);

    float4 ra0, ra1;
    float4 rw0, rw1;

    auto ldA = [&](int kc) {
        if (kc < NCH) {
            int kb = kc*16;
            ra0 = *(const float4*)(g_hbuf + (size_t)li0*FF + kb + akq*4);
            ra1 = *(const float4*)(g_hbuf + (size_t)li1*FF + kb + akq*4);
        } else {
            ra0 = *(const float4*)(g_had + (size_t)li0*RR + akq*4);
            ra1 = *(const float4*)(g_had + (size_t)li1*RR + akq*4);
        }
    };
    auto ldW0 = [&](int kc) {
        if (kc < NCH) rw0 = *(const float4*)(Wd + ((size_t)e*DD + n0 + gr)*FF + kc*16 + gkq*4);
        else          rw0 = *(const float4*)(Bd + ((size_t)e*DD + n0 + gr)*RR + gkq*4);
    };
    auto ldW1 = [&](int kc) {
        if (kc < NCH) rw1 = *(const float4*)(Wd + ((size_t)e*DD + n0 + gr)*FF + kc*16 + gkq*4);
        else          rw1 = *(const float4*)(Bd + ((size_t)e*DD + n0 + gr)*RR + gkq*4);
    };
    auto sts0 = [&](int s) {
        sts_tf32x4(&As[s][ ar0*P2     + akq*4], ra0);
        sts_tf32x4(&As[s][(ar0+64)*P2 + akq*4], ra1);
        sts_tf32x4(&Ws[s][gr*P2 + gkq*4], rw0);
    };
    auto sts1 = [&](int s) {
        sts_tf32x4(&As[s][ ar0*P2     + akq*4], ra0);
        sts_tf32x4(&As[s][(ar0+64)*P2 + akq*4], ra1);
        sts_tf32x4(&Ws[s][gr*P2 + gkq*4], rw1);
    };

    float acc[4][2][4] = {};

    auto compute = [&](int s) {
        #pragma unroll
        for (int ks = 0; ks < 2; ks++) {
            int kb = ks*8 + (lane & 3);
            uint32_t a[4][4];
            #pragma unroll
            for (int mt = 0; mt < 4; mt++) {
                const uint32_t* ap = &As[s][(wm*64 + mt*16 + (lane >> 2))*P2 + kb];
                a[mt][0] = ap[0];     a[mt][2] = ap[4];
                a[mt][1] = ap[8*P2];  a[mt][3] = ap[8*P2 + 4];
            }
            #pragma unroll
            for (int nt = 0; nt < 2; nt++) {
                const uint32_t* wp = &Ws[s][(wn*16 + nt*8 + (lane >> 2))*P2 + kb];
                uint32_t w0 = wp[0], w1 = wp[4];
                #pragma unroll
                for (int mt = 0; mt < 4; mt++)
                    mma8(acc[mt][nt], a[mt], w0, w1);
            }
        }
    };

    ldW0(0); ldA(0);
    sts0(0);
    ldW1(1);
    __syncthreads();

    for (int kc = 0; kc < TCH; kc += 2) {
        if (kc + 1 < TCH) ldA(kc + 1);
        if (kc + 2 < TCH) ldW0(kc + 2);
        compute(0);
        if (kc + 1 < TCH) {
            __syncthreads();
            sts1(1);
            __syncthreads();
        }
        if (kc + 1 < TCH) {
            if (kc + 2 < TCH) ldA(kc + 2);
            if (kc + 3 < TCH) ldW1(kc + 3);
            compute(1);
            if (kc + 2 < TCH) {
                __syncthreads();
                sts0(0);
                __syncthreads();
            }
        }
    }

    // epilogue: weighted write to slot scratch
    #pragma unroll
    for (int mt = 0; mt < 4; mt++) {
        #pragma unroll
        for (int half = 0; half < 2; half++) {
            int mrow = wm*64 + mt*16 + (lane >> 2) + half*8;
            int m = m0 + mrow;
            if (m < n_e) {
                int tok = toks[mrow]; float w = wts[mrow]; int sl = slts[mrow];
                float* orow = g_scr + ((size_t)sl*SQ + tok)*DD + n0;
                #pragma unroll
                for (int nt = 0; nt < 2; nt++) {
                    int col = wn*16 + nt*8 + 2*(lane & 3);
                    float2 v;
                    v.x = acc[mt][nt][half*2+0] * w;
                    v.y = acc[mt][nt][half*2+1] * w;
                    *(float2*)(orow + col) = v;
                }
            }
        }
    }
}

// ================= E5: slot combine =================
__global__ void e5_combine(float* __restrict__ out) {
    int i = blockIdx.x*blockDim.x + threadIdx.x;
    const float4* a = (const float4*)g_scr;
    const float4* b = (const float4*)(g_scr + (size_t)SQ*DD);
    float4 va = a[i], vb = b[i];
    ((float4*)out)[i] = make_float4(va.x+vb.x, va.y+vb.y, va.z+vb.z, va.w+vb.w);
}

// ================= launch =================
extern "C" void kernel_launch(void* const* d_in, const int* in_sizes, int n_in,
                              void* d_out, int out_size) {
    const float* x       = (const float*)d_in[0];
    const float* hist    = (const float*)d_in[1];
    const float* persona = (const float*)d_in[2];
    const float* fw1x    = (const float*)d_in[3];
    const float* fw1h    = (const float*)d_in[4];
    const float* fw1p    = (const float*)d_in[5];
    const float* fb1     = (const float*)d_in[6];
    const float* fw2     = (const float*)d_in[7];
    const float* fb2     = (const float*)d_in[8];
    const float* lng     = (const float*)d_in[9];
    const float* lnb     = (const float*)d_in[10];
    const float* gw      = (const float*)d_in[11];
    const float* gb      = (const float*)d_in[12];
    const float* Wg      = (const float*)d_in[13];
    const float* Wu      = (const float*)d_in[14];
    const float* Wd      = (const float*)d_in[15];
    const float* Ag      = (const float*)d_in[16];
    const float* Bg      = (const float*)d_in[17];
    const float* Au      = (const float*)d_in[18];
    const float* Bu      = (const float*)d_in[19];
    const float* Ad      = (const float*)d_in[20];
    const float* Bd      = (const float*)d_in[21];
    float* out = (float*)d_out;

    k0_hist_persona<<<1, 128>>>(hist, persona, fw1h, fw1p, lng, lnb, gw);
    k1t<<<dim3(2, 8), 256>>>(x, fw1x);
    k2b<<<dim3(SQ/8, EE), 256>>>(fb1, fw2, fb2, lng, gw, gb);
    k3_route<<<1, SQ>>>(out, out_size);
    e1_xa<<<dim3(SQ, EE), 128>>>(x, Ag, Au);
    e2_mma<<<dim3(4, FF/64, EE), 256>>>(x, Wg, Wu, Bg, Bu);
    e3_ha<<<dim3(SQ, EE), 128>>>(Ad);
    e4_mma<<<dim3(4, DD/64, EE), 256>>>(Wd, Bd);
    e5_combine<<<(SQ*DD)/(256*4), 256>>>(out);
}